// round 12
// baseline (speedup 1.0000x reference)
#include <cuda_runtime.h>
#include <cstdint>

// CRF forward scan, 512 blocks x 128 threads (4 warps -> all 4 SMSPs), ONE
// batch per block. Thread 32w+l computes matvec partials for columns l and
// l+32 over v rows [16w,16w+16) (16 FFMA2/thread). Partials combined via
// s_part[w][j]. Thread t carries alpha of state t&63 (upper half duplicates
// the cheap scalar tail to keep SMSPs symmetric). Shift m = stale-by-1
// alpha[1] (block-uniform; LSE shift-invariant). alpha base-2 scaled,
// ex2/lg2 approx PTX. feats/masks staged via cp.async 3-buffer pipeline.

#define TT 64
#define CHUNK 16
#define L2E 1.4426950408889634f
#define LN2 0.6931471805599453f
typedef unsigned long long u64;

__device__ float g_Wt[TT * TT];  // g_Wt[j*64+i] = exp(trans[i][j]-c_j)
__device__ float g_c2[TT];       // c_j * log2(e)

__device__ __forceinline__ void unpack2(u64 v, float& lo, float& hi) {
    asm("mov.b64 {%0, %1}, %2;" : "=f"(lo), "=f"(hi) : "l"(v));
}
__device__ __forceinline__ u64 ffma2(u64 a, u64 b, u64 c) {
    u64 d; asm("fma.rn.f32x2 %0, %1, %2, %3;" : "=l"(d) : "l"(a), "l"(b), "l"(c)); return d;
}
__device__ __forceinline__ u64 fadd2(u64 a, u64 b) {
    u64 d; asm("add.rn.f32x2 %0, %1, %2;" : "=l"(d) : "l"(a), "l"(b)); return d;
}
__device__ __forceinline__ float ex2f(float x) {
    float y; asm("ex2.approx.f32 %0, %1;" : "=f"(y) : "f"(x)); return y;
}
__device__ __forceinline__ float lg2f(float x) {
    float y; asm("lg2.approx.f32 %0, %1;" : "=f"(y) : "f"(x)); return y;
}
__device__ __forceinline__ uint32_t smem_u32(const void* p) {
    uint32_t a;
    asm("{ .reg .u64 t; cvta.to.shared.u64 t, %1; cvt.u32.u64 %0, t; }" : "=r"(a) : "l"(p));
    return a;
}

// ---------------------------------------------------------------------------
__global__ void crf_prep_kernel(const float* __restrict__ trans) {
    int j = threadIdx.x;
    float c = -3.402823466e+38f;
    #pragma unroll
    for (int i = 0; i < TT; i++) c = fmaxf(c, trans[i * TT + j]);
    g_c2[j] = c * L2E;
    #pragma unroll
    for (int i = 0; i < TT; i++) g_Wt[j * TT + i] = __expf(trans[i * TT + j] - c);
}

// ---------------------------------------------------------------------------
__global__ void __launch_bounds__(128, 3) crf_scan_kernel(
    const float* __restrict__ feats,   // [B, S, 64]
    const float* __restrict__ masks,   // [B, S]
    float* __restrict__ out,           // [B, 64]
    int Sdim)
{
    const int b    = blockIdx.x;
    const int tid  = threadIdx.x;       // 0..127
    const int w    = tid >> 5;          // warp 0..3 -> SMSP w
    const int lane = tid & 31;
    const int st   = tid & 63;          // owned state (duplicated in upper half)

    __shared__ alignas(16) float s_feat[3][CHUNK][TT];   // 12 KB staged feats
    __shared__ float s_mask[3][CHUNK];
    __shared__ alignas(16) float s_v[2][TT];             // v, double buffered
    __shared__ float s_part[2][4][TT];                   // [buf][warp][state]
    __shared__ float s_mring[2];                         // stale alpha[1] ring

    // W for columns lane and lane+32, rows [16w, 16w+16), pre-packed u64.
    u64 wA[8], wB[8];
    {
        const ulonglong2* pa =
            reinterpret_cast<const ulonglong2*>(&g_Wt[lane * TT + 16 * w]);
        const ulonglong2* pb =
            reinterpret_cast<const ulonglong2*>(&g_Wt[(lane + 32) * TT + 16 * w]);
        #pragma unroll
        for (int q = 0; q < 4; q++) {
            ulonglong2 ua = pa[q];
            wA[2 * q]     = ua.x;
            wA[2 * q + 1] = ua.y;
            ulonglong2 ub = pb[q];
            wB[2 * q]     = ub.x;
            wB[2 * q + 1] = ub.y;
        }
    }
    const float cj2 = g_c2[st];

    const float* fbp = feats + (size_t)b * Sdim * TT;
    const float* mbp = masks + (size_t)b * Sdim;
    const uint32_t feat_s0 = smem_u32(&s_feat[0][0][0]);
    const uint32_t mask_s0 = smem_u32(&s_mask[0][0]);

    const int NC = (Sdim + CHUNK - 1) / CHUNK;

    // Stage chunk c into buffer c%3 — fully async, 128 threads.
    auto stage = [&](int c) {
        const int base = c * CHUNK;
        const int bufo = (c % 3) * CHUNK * TT;
        #pragma unroll
        for (int q = 0; q < 2; q++) {
            int g   = q * 128 + tid;       // 16B granule 0..255
            int row = g >> 4;
            int col = (g & 15) << 2;
            int gr  = base + row; if (gr >= Sdim) gr = Sdim - 1;
            const float* src = fbp + (size_t)gr * TT + col;
            uint32_t dst = feat_s0 + (uint32_t)(bufo + row * TT + col) * 4u;
            asm volatile("cp.async.cg.shared.global [%0], [%1], 16;" :: "r"(dst), "l"(src));
        }
        if (tid < CHUNK) {
            int gr = base + tid; if (gr >= Sdim) gr = Sdim - 1;
            const float* src = mbp + gr;
            uint32_t dst = mask_s0 + (uint32_t)((c % 3) * CHUNK + tid) * 4u;
            asm volatile("cp.async.ca.shared.global [%0], [%1], 4;" :: "r"(dst), "l"(src));
        }
    };

    stage(0);
    asm volatile("cp.async.commit_group;");
    if (NC > 1) stage(1);
    asm volatile("cp.async.commit_group;");
    asm volatile("cp.async.wait_group 1;");
    __syncthreads();

    float alpha = s_feat[0][0][st] * L2E;    // base-2 scaled alpha0

    // Seed shift ring: slot 1 read at t=1 (slot = r&1).
    if (tid == 1) s_mring[1] = alpha;
    __syncthreads();
    float m = s_mring[1];

    for (int c = 0; c < NC; c++) {
        if (c > 0) asm volatile("cp.async.wait_group 1;");
        if (c + 2 < NC) stage(c + 2);
        asm volatile("cp.async.commit_group;");
        __syncthreads();

        #pragma unroll
        for (int r = 0; r < CHUNK; r++) {
            const int t = c * CHUNK + r;
            if (t >= 1 && t < Sdim) {
                // Chain head: exp2 with stale shift; lower half publishes v.
                const float v = ex2f(alpha - m);
                if (tid < TT) s_v[r & 1][tid] = v;

                // Publish alpha[1] for step t+1's shift.
                if (tid == 1) s_mring[(r & 1) ^ 1] = alpha;

                // Off-chain: staged feat/mask, blend precompute.
                const float ft  = s_feat[c % 3][r][st];
                const float mk  = s_mask[c % 3][r];
                const float pre = fmaf(ft, L2E, cj2 + m);
                const float t0  = fmaf(mk, pre - alpha, alpha);

                __syncthreads();   // v visible to all warps

                // Quarter matvec: rows [16w,16w+16) for columns lane, lane+32.
                const ulonglong2* vp =
                    reinterpret_cast<const ulonglong2*>(&s_v[r & 1][16 * w]);
                u64 accA[4] = {0ull, 0ull, 0ull, 0ull};
                u64 accB[4] = {0ull, 0ull, 0ull, 0ull};
                #pragma unroll
                for (int q = 0; q < 4; q++) {
                    ulonglong2 u = vp[q];
                    accA[(2 * q) & 3]     = ffma2(u.x, wA[2 * q],     accA[(2 * q) & 3]);
                    accA[(2 * q + 1) & 3] = ffma2(u.y, wA[2 * q + 1], accA[(2 * q + 1) & 3]);
                    accB[(2 * q) & 3]     = ffma2(u.x, wB[2 * q],     accB[(2 * q) & 3]);
                    accB[(2 * q + 1) & 3] = ffma2(u.y, wB[2 * q + 1], accB[(2 * q + 1) & 3]);
                }
                u64 sA = fadd2(fadd2(accA[0], accA[1]), fadd2(accA[2], accA[3]));
                u64 sB = fadd2(fadd2(accB[0], accB[1]), fadd2(accB[2], accB[3]));
                float al, ah, bl, bh;
                unpack2(sA, al, ah);
                unpack2(sB, bl, bh);
                s_part[r & 1][w][lane]      = al + ah;   // quarter-partial col lane
                s_part[r & 1][w][lane + 32] = bl + bh;   // quarter-partial col lane+32

                __syncthreads();   // all quarter-partials visible

                // Tail: combine 4 quarter-partials, log2, blend.
                const float p0 = s_part[r & 1][0][st];
                const float p1 = s_part[r & 1][1][st];
                const float p2 = s_part[r & 1][2][st];
                const float p3 = s_part[r & 1][3][st];
                const float P  = (p0 + p1) + (p2 + p3);
                alpha = fmaf(lg2f(P), mk, t0);
                m = s_mring[(r & 1) ^ 1];
            }
        }
    }

    if (tid < TT) out[(size_t)b * TT + tid] = alpha * LN2;
}

// ---------------------------------------------------------------------------
extern "C" void kernel_launch(void* const* d_in, const int* in_sizes, int n_in,
                              void* d_out, int out_size) {
    const float* feats = (const float*)d_in[0];
    const float* masks = (const float*)d_in[1];
    const float* trans = (const float*)d_in[2];
    float* out = (float*)d_out;

    const int Bn   = out_size / TT;
    const int Sdim = in_sizes[0] / (Bn * TT);

    crf_prep_kernel<<<1, TT>>>(trans);
    crf_scan_kernel<<<Bn, 128>>>(feats, masks, out, Sdim);
}

// round 14
// speedup vs baseline: 1.0282x; 1.0282x over previous
#include <cuda_runtime.h>
#include <cstdint>

// CRF forward scan, 512 blocks x 128 threads (4 warps -> 4 SMSPs), ONE batch
// per block, ONE __syncthreads per step. Warp w owns states [16w,16w+16);
// each state is carried by TWO threads (st = 16w + (l>>1), h = l&1): thread
// computes column st partial over v-rows [32h,32h+32) (16 FFMA2), combined
// with one shfl_xor(1) — no second barrier. Shift m = stale alpha[1]
// (block-uniform; LSE shift-invariant). alpha base-2 scaled, ex2/lg2 approx.
// feats/masks staged via cp.async 3-buffer pipeline.

#define TT 64
#define CHUNK 16
#define L2E 1.4426950408889634f
#define LN2 0.6931471805599453f
typedef unsigned long long u64;

__device__ float g_Wt[TT * TT];  // g_Wt[j*64+i] = exp(trans[i][j]-c_j)
__device__ float g_c2[TT];       // c_j * log2(e)

__device__ __forceinline__ void unpack2(u64 v, float& lo, float& hi) {
    asm("mov.b64 {%0, %1}, %2;" : "=f"(lo), "=f"(hi) : "l"(v));
}
__device__ __forceinline__ u64 ffma2(u64 a, u64 b, u64 c) {
    u64 d; asm("fma.rn.f32x2 %0, %1, %2, %3;" : "=l"(d) : "l"(a), "l"(b), "l"(c)); return d;
}
__device__ __forceinline__ u64 fadd2(u64 a, u64 b) {
    u64 d; asm("add.rn.f32x2 %0, %1, %2;" : "=l"(d) : "l"(a), "l"(b)); return d;
}
__device__ __forceinline__ float ex2f(float x) {
    float y; asm("ex2.approx.f32 %0, %1;" : "=f"(y) : "f"(x)); return y;
}
__device__ __forceinline__ float lg2f(float x) {
    float y; asm("lg2.approx.f32 %0, %1;" : "=f"(y) : "f"(x)); return y;
}
__device__ __forceinline__ uint32_t smem_u32(const void* p) {
    uint32_t a;
    asm("{ .reg .u64 t; cvta.to.shared.u64 t, %1; cvt.u32.u64 %0, t; }" : "=r"(a) : "l"(p));
    return a;
}

// ---------------------------------------------------------------------------
__global__ void crf_prep_kernel(const float* __restrict__ trans) {
    int j = threadIdx.x;
    float c = -3.402823466e+38f;
    #pragma unroll
    for (int i = 0; i < TT; i++) c = fmaxf(c, trans[i * TT + j]);
    g_c2[j] = c * L2E;
    #pragma unroll
    for (int i = 0; i < TT; i++) g_Wt[j * TT + i] = __expf(trans[i * TT + j] - c);
}

// ---------------------------------------------------------------------------
__global__ void __launch_bounds__(128, 4) crf_scan_kernel(
    const float* __restrict__ feats,   // [B, S, 64]
    const float* __restrict__ masks,   // [B, S]
    float* __restrict__ out,           // [B, 64]
    int Sdim)
{
    const int b    = blockIdx.x;
    const int tid  = threadIdx.x;       // 0..127
    const int w    = tid >> 5;          // warp -> SMSP
    const int lane = tid & 31;
    const int st   = 16 * w + (lane >> 1);  // owned state (2 threads each)
    const int h    = lane & 1;               // which v-half this thread reduces

    __shared__ alignas(16) float s_feat[3][CHUNK][TT];   // 12 KB staged feats
    __shared__ float s_mask[3][CHUNK];
    __shared__ alignas(16) float s_v[2][2][36];          // [buf][half][state+pad]
    __shared__ float s_mring[2];                         // stale alpha[1] ring

    // W column st, rows [32h, 32h+32) — 32 floats = 16 packed u64 pairs.
    u64 wA[16];
    {
        const ulonglong2* pa =
            reinterpret_cast<const ulonglong2*>(&g_Wt[st * TT + 32 * h]);
        #pragma unroll
        for (int q = 0; q < 8; q++) {
            ulonglong2 ua = pa[q];
            wA[2 * q]     = ua.x;
            wA[2 * q + 1] = ua.y;
        }
    }
    const float cj2 = g_c2[st];

    const float* fbp = feats + (size_t)b * Sdim * TT;
    const float* mbp = masks + (size_t)b * Sdim;
    const uint32_t feat_s0 = smem_u32(&s_feat[0][0][0]);
    const uint32_t mask_s0 = smem_u32(&s_mask[0][0]);

    const int NC = (Sdim + CHUNK - 1) / CHUNK;

    // Stage chunk c into buffer c%3 — fully async, 128 threads.
    auto stage = [&](int c) {
        const int base = c * CHUNK;
        const int bufo = (c % 3) * CHUNK * TT;
        #pragma unroll
        for (int q = 0; q < 2; q++) {
            int g   = q * 128 + tid;       // 16B granule 0..255
            int row = g >> 4;
            int col = (g & 15) << 2;
            int gr  = base + row; if (gr >= Sdim) gr = Sdim - 1;
            const float* src = fbp + (size_t)gr * TT + col;
            uint32_t dst = feat_s0 + (uint32_t)(bufo + row * TT + col) * 4u;
            asm volatile("cp.async.cg.shared.global [%0], [%1], 16;" :: "r"(dst), "l"(src));
        }
        if (tid < CHUNK) {
            int gr = base + tid; if (gr >= Sdim) gr = Sdim - 1;
            const float* src = mbp + gr;
            uint32_t dst = mask_s0 + (uint32_t)((c % 3) * CHUNK + tid) * 4u;
            asm volatile("cp.async.ca.shared.global [%0], [%1], 4;" :: "r"(dst), "l"(src));
        }
    };

    stage(0);
    asm volatile("cp.async.commit_group;");
    if (NC > 1) stage(1);
    asm volatile("cp.async.commit_group;");
    asm volatile("cp.async.wait_group 1;");
    __syncthreads();

    float alpha = s_feat[0][0][st] * L2E;    // base-2 scaled alpha0

    // Seed shift ring: slot 1 read at t=1.
    if (tid == 2) s_mring[1] = alpha;        // tid 2 <=> st=1, h=0
    __syncthreads();
    float m = s_mring[1];

    for (int c = 0; c < NC; c++) {
        if (c > 0) asm volatile("cp.async.wait_group 1;");
        if (c + 2 < NC) stage(c + 2);
        asm volatile("cp.async.commit_group;");
        __syncthreads();

        #pragma unroll
        for (int r = 0; r < CHUNK; r++) {
            const int t = c * CHUNK + r;
            if (t >= 1 && t < Sdim) {                    // uniform guard
                // Chain head: exp2 with stale shift; one thread per state
                // publishes v into the split/padded v buffer.
                const float v = ex2f(alpha - m);
                if (h == 0) s_v[r & 1][st >> 5][st & 31] = v;

                // Publish alpha[1] for step t+1's shift.
                if (tid == 2) s_mring[(r & 1) ^ 1] = alpha;

                // Off-chain: staged feat/mask, blend precompute.
                const float ft  = s_feat[c % 3][r][st];
                const float mk  = s_mask[c % 3][r];
                const float pre = fmaf(ft, L2E, cj2 + m);
                const float t0  = fmaf(mk, pre - alpha, alpha);

                __syncthreads();   // all v halves visible (the ONLY barrier)

                // Half-column matvec: rows [32h,32h+32) of column st.
                const ulonglong2* vp =
                    reinterpret_cast<const ulonglong2*>(&s_v[r & 1][h][0]);
                u64 acc[4] = {0ull, 0ull, 0ull, 0ull};
                #pragma unroll
                for (int q = 0; q < 8; q++) {
                    ulonglong2 u = vp[q];
                    acc[(2 * q) & 3]     = ffma2(u.x, wA[2 * q],     acc[(2 * q) & 3]);
                    acc[(2 * q + 1) & 3] = ffma2(u.y, wA[2 * q + 1], acc[(2 * q + 1) & 3]);
                }
                u64 s2 = fadd2(fadd2(acc[0], acc[1]), fadd2(acc[2], acc[3]));
                float lo, hi;
                unpack2(s2, lo, hi);
                const float PA = lo + hi;                // this half's partial
                const float P  = PA + __shfl_xor_sync(0xffffffffu, PA, 1);

                // Tail: log2, blend; fetch next shift.
                alpha = fmaf(lg2f(P), mk, t0);
                m = s_mring[(r & 1) ^ 1];
            }
        }
    }

    if (h == 0) out[(size_t)b * TT + st] = alpha * LN2;
}

// ---------------------------------------------------------------------------
extern "C" void kernel_launch(void* const* d_in, const int* in_sizes, int n_in,
                              void* d_out, int out_size) {
    const float* feats = (const float*)d_in[0];
    const float* masks = (const float*)d_in[1];
    const float* trans = (const float*)d_in[2];
    float* out = (float*)d_out;

    const int Bn   = out_size / TT;
    const int Sdim = in_sizes[0] / (Bn * TT);

    crf_prep_kernel<<<1, TT>>>(trans);
    crf_scan_kernel<<<Bn, 128>>>(feats, masks, out, Sdim);
}

// round 15
// speedup vs baseline: 1.3553x; 1.3180x over previous
#include <cuda_runtime.h>
#include <cstdint>

// CRF forward scan, 512 blocks x 64 threads (best shape: 2-warp sync domain).
// Thread tid owns state tid. Each thread computes f32x2-packed partial sums
// over its own warp's v-half (rows [32*w2,32*w2+32)) for columns tid (kept)
// and tid^32 (published as ONE u64). One __syncthreads per step.
// Shift m = stale-by-1 alpha[1] (block-uniform; LSE shift-invariant).
// alpha base-2 scaled; ex2/lg2 approx PTX. feats/masks via cp.async 3-buffer.
// Mask applied as select (masks are exactly 0/1).

#define TT 64
#define CHUNK 16
#define L2E 1.4426950408889634f
#define LN2 0.6931471805599453f
typedef unsigned long long u64;

__device__ float g_Wt[TT * TT];  // g_Wt[j*64+i] = exp(trans[i][j]-c_j)
__device__ float g_c2[TT];       // c_j * log2(e)

__device__ __forceinline__ void unpack2(u64 v, float& lo, float& hi) {
    asm("mov.b64 {%0, %1}, %2;" : "=f"(lo), "=f"(hi) : "l"(v));
}
__device__ __forceinline__ u64 ffma2(u64 a, u64 b, u64 c) {
    u64 d; asm("fma.rn.f32x2 %0, %1, %2, %3;" : "=l"(d) : "l"(a), "l"(b), "l"(c)); return d;
}
__device__ __forceinline__ u64 fadd2(u64 a, u64 b) {
    u64 d; asm("add.rn.f32x2 %0, %1, %2;" : "=l"(d) : "l"(a), "l"(b)); return d;
}
__device__ __forceinline__ float ex2f(float x) {
    float y; asm("ex2.approx.f32 %0, %1;" : "=f"(y) : "f"(x)); return y;
}
__device__ __forceinline__ float lg2f(float x) {
    float y; asm("lg2.approx.f32 %0, %1;" : "=f"(y) : "f"(x)); return y;
}
__device__ __forceinline__ uint32_t smem_u32(const void* p) {
    uint32_t a;
    asm("{ .reg .u64 t; cvta.to.shared.u64 t, %1; cvt.u32.u64 %0, t; }" : "=r"(a) : "l"(p));
    return a;
}

// ---------------------------------------------------------------------------
__global__ void crf_prep_kernel(const float* __restrict__ trans) {
    int j = threadIdx.x;
    float c = -3.402823466e+38f;
    #pragma unroll
    for (int i = 0; i < TT; i++) c = fmaxf(c, trans[i * TT + j]);
    g_c2[j] = c * L2E;
    #pragma unroll
    for (int i = 0; i < TT; i++) g_Wt[j * TT + i] = __expf(trans[i * TT + j] - c);
}

// ---------------------------------------------------------------------------
__global__ void __launch_bounds__(64) crf_scan_kernel(
    const float* __restrict__ feats,   // [B, S, 64]
    const float* __restrict__ masks,   // [B, S]
    float* __restrict__ out,           // [B, 64]
    int Sdim)
{
    const int b   = blockIdx.x;
    const int tid = threadIdx.x;
    const int w2  = tid >> 5;

    __shared__ alignas(16) float s_feat[3][CHUNK][TT];   // 12 KB staged feats
    __shared__ float s_mask[3][CHUNK];
    __shared__ alignas(16) float s_v[TT];                // SINGLE buffer (BAR-ordered)
    __shared__ u64 s_part[2][TT];                        // packed partials, dbl-buf
    __shared__ float s_mring[2];                         // stale alpha[1] ring

    // W columns tid (own) and tid^32, rows [32*w2, 32*w2+32), pre-packed u64.
    u64 wA[16], wB[16];
    {
        const ulonglong2* pa =
            reinterpret_cast<const ulonglong2*>(&g_Wt[tid * TT + 32 * w2]);
        const ulonglong2* pb =
            reinterpret_cast<const ulonglong2*>(&g_Wt[(tid ^ 32) * TT + 32 * w2]);
        #pragma unroll
        for (int q = 0; q < 8; q++) {
            ulonglong2 ua = pa[q];
            wA[2 * q]     = ua.x;
            wA[2 * q + 1] = ua.y;
            ulonglong2 ub = pb[q];
            wB[2 * q]     = ub.x;
            wB[2 * q + 1] = ub.y;
        }
    }
    const float cj2 = g_c2[tid];

    const float* fbp = feats + (size_t)b * Sdim * TT;
    const float* mbp = masks + (size_t)b * Sdim;
    const uint32_t feat_s0 = smem_u32(&s_feat[0][0][0]);
    const uint32_t mask_s0 = smem_u32(&s_mask[0][0]);

    const int NC   = (Sdim + CHUNK - 1) / CHUNK;
    const int tail = Sdim - (NC - 1) * CHUNK;   // steps in last chunk (1..CHUNK)

    auto stage = [&](int c) {
        const int base = c * CHUNK;
        const int bufo = (c % 3) * CHUNK * TT;
        #pragma unroll
        for (int q = 0; q < 4; q++) {
            int g   = q * 64 + tid;        // 16B granule 0..255
            int row = g >> 4;
            int col = (g & 15) << 2;
            int gr  = base + row; if (gr >= Sdim) gr = Sdim - 1;
            const float* src = fbp + (size_t)gr * TT + col;
            uint32_t dst = feat_s0 + (uint32_t)(bufo + row * TT + col) * 4u;
            asm volatile("cp.async.cg.shared.global [%0], [%1], 16;" :: "r"(dst), "l"(src));
        }
        if (tid < CHUNK) {
            int gr = base + tid; if (gr >= Sdim) gr = Sdim - 1;
            const float* src = mbp + gr;
            uint32_t dst = mask_s0 + (uint32_t)((c % 3) * CHUNK + tid) * 4u;
            asm volatile("cp.async.ca.shared.global [%0], [%1], 4;" :: "r"(dst), "l"(src));
        }
    };

    stage(0);
    asm volatile("cp.async.commit_group;");
    if (NC > 1) stage(1);
    asm volatile("cp.async.commit_group;");
    asm volatile("cp.async.wait_group 1;");
    __syncthreads();

    float alpha = s_feat[0][0][tid] * L2E;   // base-2 scaled alpha0

    // Seed shift ring: slot 1 read at t=1 (slot = r&1).
    if (tid == 1) s_mring[1] = alpha;
    __syncthreads();
    float m = s_mring[1];

    // One CRF step. Index args are compile-time constants in the main loop.
    auto step = [&](const float* fchunk, const float* mchunk, int r) {
        // Chain head: exp2 with stale shift; publish own v (constant addr).
        const float v = ex2f(alpha - m);
        s_v[tid] = v;

        // Publish alpha[1] for step t+1's shift.
        if (tid == 1) s_mring[(r & 1) ^ 1] = alpha;

        // Off-chain: staged feat/mask, pre-activation.
        const float ft  = fchunk[r * TT + tid];
        const float mk  = mchunk[r];
        const float pre = fmaf(ft, L2E, cj2 + m);

        __syncwarp();

        // Own-half matvec for columns tid and tid^32 (2 accs per column).
        const ulonglong2* vp =
            reinterpret_cast<const ulonglong2*>(&s_v[32 * w2]);
        u64 a0 = 0ull, a1 = 0ull, b0 = 0ull, b1 = 0ull;
        #pragma unroll
        for (int q = 0; q < 8; q++) {
            ulonglong2 u = vp[q];
            a0 = ffma2(u.x, wA[2 * q],     a0);
            a1 = ffma2(u.y, wA[2 * q + 1], a1);
            b0 = ffma2(u.x, wB[2 * q],     b0);
            b1 = ffma2(u.y, wB[2 * q + 1], b1);
        }
        const u64 sA = fadd2(a0, a1);       // own column, own half (packed)
        const u64 sB = fadd2(b0, b1);       // partner column, own half

        s_part[r & 1][tid ^ 32] = sB;       // publish packed partial

        __syncthreads();                    // the ONLY block barrier

        // Tail: packed combine, horizontal add, log2, masked select.
        const u64 comb = fadd2(sA, s_part[r & 1][tid]);
        float lo, hi;
        unpack2(comb, lo, hi);
        const float P = lo + hi;
        const float na = pre + lg2f(P);
        alpha = (mk != 0.0f) ? na : alpha;
        m = s_mring[(r & 1) ^ 1];
    };

    for (int c = 0; c < NC; c++) {
        if (c > 0) asm volatile("cp.async.wait_group 1;");
        if (c + 2 < NC) stage(c + 2);
        asm volatile("cp.async.commit_group;");             // uniform count
        __syncthreads();

        const float* fchunk = &s_feat[c % 3][0][0];
        const float* mchunk = &s_mask[c % 3][0];

        if (c + 1 < NC) {
            // Full chunk: guards fold away for unrolled r >= 1.
            #pragma unroll
            for (int r = 0; r < CHUNK; r++) {
                if (r == 0 && c == 0) continue;   // skip t = 0 only
                step(fchunk, mchunk, r);
            }
        } else {
            for (int r = 0; r < tail; r++) {
                if (r == 0 && c == 0) continue;
                step(fchunk, mchunk, r);
            }
        }
    }

    out[(size_t)b * TT + tid] = alpha * LN2;
}

// ---------------------------------------------------------------------------
extern "C" void kernel_launch(void* const* d_in, const int* in_sizes, int n_in,
                              void* d_out, int out_size) {
    const float* feats = (const float*)d_in[0];
    const float* masks = (const float*)d_in[1];
    const float* trans = (const float*)d_in[2];
    float* out = (float*)d_out;

    const int Bn   = out_size / TT;
    const int Sdim = in_sizes[0] / (Bn * TT);

    crf_prep_kernel<<<1, TT>>>(trans);
    crf_scan_kernel<<<Bn, TT>>>(feats, masks, out, Sdim);
}